// round 15
// baseline (speedup 1.0000x reference)
#include <cuda_runtime.h>
#include <cuda.h>
#include <cstdint>

// GatherBlock: out[m, :, :, :] = x[b[m], :, yb[m]*16 : yb[m]*16+16, xb[m]*16 : xb[m]*16+16]
// x: (8, 64, 256, 256) fp32, indices: (1024, 3) int32, out: (1024, 64, 16, 16) fp32.
//
// R15: TMA path. The tile is a 3D TMA box [16,16,32]f32 on tensor
// (W=256,H=256,N*C=512); it lands in SMEM in exactly out[m]'s contiguous
// layout, so the write is a plain 32KB cp.async.bulk store. Per CTA: 2 TMA
// loads + 2 bulk stores. 1024 CTAs (tile-sorted), 32 threads, 64KB smem ->
// 3 CTAs/SM, 192KB reads in flight/SM. Tensor map built host-side via
// cuTensorMapEncodeTiled resolved through cudaGetDriverEntryPoint (no -lcuda
// needed); falls back to the proven R8 LDG kernel if unavailable.

static constexpr int C = 64;
static constexpr int H = 256;
static constexpr int W = 256;
static constexpr int BH = 16;
static constexpr int BW = 16;
static constexpr int CHW = C * H * W;
static constexpr int HW = H * W;
static constexpr int VEC_PER_M = C * BH * BW / 4;     // 4096 float4
static constexpr int M_MAX = 1024;
static constexpr int BINS = 2048;

// TMA kernel config
static constexpr int HALF_BYTES = 32768;              // 32 channels * 16*16*4
static constexpr int SMEM_BYTES = 2 * HALF_BYTES + 64;

// Fallback (R8) config
static constexpr int FB_SPLIT = 4;
static constexpr int FB_TPB = 128;
static constexpr int FB_VPC = VEC_PER_M / FB_SPLIT;   // 1024
static constexpr int FB_LPT = FB_VPC / FB_TPB;        // 8

__device__ int g_perm[M_MAX];

// ---------------- sort (counting sort by tile id; ~free) ----------------
__global__ __launch_bounds__(M_MAX, 1)
void sort_indices_kernel(const int* __restrict__ idx, int M)
{
    __shared__ unsigned hist[BINS];
    __shared__ unsigned warpsum[32];

    const int t = threadIdx.x;
    const int lane = t & 31;
    const int wid = t >> 5;

    hist[2 * t] = 0;
    hist[2 * t + 1] = 0;
    __syncthreads();

    int key = 0;
    if (t < M) {
        const int b  = idx[3 * t + 0];
        const int yb = idx[3 * t + 1];
        const int xb = idx[3 * t + 2];
        key = (b << 8) | (yb << 4) | xb;
        atomicAdd(&hist[key], 1u);
    }
    __syncthreads();

    const unsigned a = hist[2 * t];
    const unsigned bcnt = hist[2 * t + 1];
    const unsigned s = a + bcnt;

    unsigned incl = s;
#pragma unroll
    for (int d = 1; d < 32; d <<= 1) {
        const unsigned n = __shfl_up_sync(0xFFFFFFFFu, incl, d);
        if (lane >= d) incl += n;
    }
    const unsigned thr_excl = incl - s;
    if (lane == 31) warpsum[wid] = incl;
    __syncthreads();

    if (wid == 0) {
        unsigned v = warpsum[lane];
        unsigned pv = v;
#pragma unroll
        for (int d = 1; d < 32; d <<= 1) {
            const unsigned n = __shfl_up_sync(0xFFFFFFFFu, pv, d);
            if (lane >= d) pv += n;
        }
        warpsum[lane] = pv - v;
    }
    __syncthreads();

    const unsigned base = warpsum[wid] + thr_excl;
    hist[2 * t]     = base;
    hist[2 * t + 1] = base + a;
    __syncthreads();

    if (t < M) {
        const unsigned pos = atomicAdd(&hist[key], 1u);
        g_perm[pos] = t;
    }
}

// ---------------- TMA gather ----------------
__device__ __forceinline__ uint32_t smem_u32(const void* p)
{
    uint32_t a;
    asm("{ .reg .u64 t; cvta.to.shared.u64 t, %1; cvt.u32.u64 %0, t; }"
        : "=r"(a) : "l"(p));
    return a;
}

__device__ __forceinline__ void mbar_init(uint32_t addr, uint32_t cnt)
{
    asm volatile("mbarrier.init.shared::cta.b64 [%0], %1;" :: "r"(addr), "r"(cnt) : "memory");
}

__device__ __forceinline__ void mbar_expect_tx(uint32_t addr, uint32_t bytes)
{
    asm volatile("mbarrier.arrive.expect_tx.shared::cta.b64 _, [%0], %1;"
                 :: "r"(addr), "r"(bytes) : "memory");
}

__device__ __forceinline__ void mbar_wait(uint32_t addr)
{
    asm volatile(
        "{\n\t"
        ".reg .pred P;\n\t"
        "LW_%=:\n\t"
        "mbarrier.try_wait.parity.shared::cta.b64 P, [%0], 0;\n\t"
        "@P bra LD_%=;\n\t"
        "bra LW_%=;\n\t"
        "LD_%=:\n\t"
        "}"
        :: "r"(addr) : "memory");
}

__device__ __forceinline__ void tma_load3d(uint32_t smem_dst, const CUtensorMap* map,
                                           int cx, int cy, int cz, uint32_t mbar)
{
    asm volatile(
        "cp.async.bulk.tensor.3d.shared::cta.global.tile.mbarrier::complete_tx::bytes "
        "[%0], [%1, {%2, %3, %4}], [%5];"
        :: "r"(smem_dst), "l"(map), "r"(cx), "r"(cy), "r"(cz), "r"(mbar)
        : "memory");
}

__device__ __forceinline__ void bulk_store(float* gdst, uint32_t smem_src, uint32_t bytes)
{
    asm volatile(
        "cp.async.bulk.global.shared::cta.bulk_group [%0], [%1], %2;"
        :: "l"(gdst), "r"(smem_src), "r"(bytes)
        : "memory");
}

__global__ __launch_bounds__(32)
void gather_tma_kernel(const __grid_constant__ CUtensorMap tmap,
                       const int* __restrict__ idx,
                       float* __restrict__ out)
{
    extern __shared__ __align__(128) char smem[];
    const uint32_t sbase = smem_u32(smem);
    const uint32_t mb0 = sbase + 2 * HALF_BYTES;
    const uint32_t mb1 = mb0 + 16;

    const int m = g_perm[blockIdx.x];
    const int b  = idx[3 * m + 0];
    const int yb = idx[3 * m + 1];
    const int xb = idx[3 * m + 2];

    float* dst = out + (size_t)m * (VEC_PER_M * 4);

    if (threadIdx.x == 0) {
        mbar_init(mb0, 1);
        mbar_init(mb1, 1);
        // single warp, single thread issues everything; init->use ordered
        // within the thread, no cross-thread visibility needed.
        mbar_expect_tx(mb0, HALF_BYTES);
        tma_load3d(sbase, &tmap, xb * BW, yb * BH, b * C, mb0);
        mbar_expect_tx(mb1, HALF_BYTES);
        tma_load3d(sbase + HALF_BYTES, &tmap, xb * BW, yb * BH, b * C + 32, mb1);

        mbar_wait(mb0);
        bulk_store(dst, sbase, HALF_BYTES);
        asm volatile("cp.async.bulk.commit_group;" ::: "memory");

        mbar_wait(mb1);
        bulk_store(dst + HALF_BYTES / 4, sbase + HALF_BYTES, HALF_BYTES);
        asm volatile("cp.async.bulk.commit_group;" ::: "memory");
        asm volatile("cp.async.bulk.wait_group 0;" ::: "memory");
    }
    __syncwarp();
}

// ---------------- fallback (R8: proven 22.6us) ----------------
__global__ __launch_bounds__(FB_TPB)
void gather_fallback_kernel(const float* __restrict__ x,
                            const int* __restrict__ idx,
                            float4* __restrict__ out)
{
    const int m = g_perm[blockIdx.x >> 2];
    const int q = blockIdx.x & 3;

    const int b  = idx[3 * m + 0];
    const int yb = idx[3 * m + 1];
    const int xb = idx[3 * m + 2];

    const float* src = x + (size_t)b * CHW + (size_t)(yb * BH) * W + (size_t)(xb * BW);
    float4* dst = out + (size_t)m * VEC_PER_M;

    const int t = threadIdx.x;
    const int v0 = q * FB_VPC + t;

    float4 r[FB_LPT];
#pragma unroll
    for (int k = 0; k < FB_LPT; k++) {
        const int v = v0 + k * FB_TPB;
        const int c = v >> 6;
        const int i = (v >> 2) & 15;
        const int j = v & 3;
        r[k] = __ldcg(reinterpret_cast<const float4*>(src + (size_t)c * HW + (size_t)i * W) + j);
    }
#pragma unroll
    for (int k = 0; k < FB_LPT; k++) {
        __stcs(dst + v0 + k * FB_TPB, r[k]);
    }
}

// ---------------- host ----------------
typedef CUresult (*EncodeFn)(CUtensorMap*, CUtensorMapDataType, cuuint32_t, void*,
                             const cuuint64_t*, const cuuint64_t*,
                             const cuuint32_t*, const cuuint32_t*,
                             CUtensorMapInterleave, CUtensorMapSwizzle,
                             CUtensorMapL2promotion, CUtensorMapFloatOOBfill);

static EncodeFn get_encoder()
{
    static EncodeFn fn = nullptr;
    static bool tried = false;
    if (!tried) {
        tried = true;
        void* p = nullptr;
#if CUDART_VERSION >= 12050
        cudaDriverEntryPointQueryResult qres;
        if (cudaGetDriverEntryPointByVersion("cuTensorMapEncodeTiled", &p, 12000,
                                             cudaEnableDefault, &qres) == cudaSuccess &&
            qres == cudaDriverEntryPointSuccess)
            fn = (EncodeFn)p;
#else
        cudaDriverEntryPointQueryResult qres;
        if (cudaGetDriverEntryPoint("cuTensorMapEncodeTiled", &p,
                                    cudaEnableDefault, &qres) == cudaSuccess &&
            qres == cudaDriverEntryPointSuccess)
            fn = (EncodeFn)p;
#endif
    }
    return fn;
}

extern "C" void kernel_launch(void* const* d_in, const int* in_sizes, int n_in,
                              void* d_out, int out_size)
{
    const float* x  = (const float*)d_in[0];
    const int* idx  = (const int*)d_in[1];

    const int M = in_sizes[1] / 3;  // 1024
    sort_indices_kernel<<<1, M_MAX>>>(idx, M);

    EncodeFn enc = get_encoder();
    bool tma_ok = false;
    CUtensorMap tmap;
    if (enc) {
        cuuint64_t dims[3]    = {(cuuint64_t)W, (cuuint64_t)H, (cuuint64_t)(8 * C)};
        cuuint64_t strides[2] = {(cuuint64_t)W * 4, (cuuint64_t)HW * 4};
        cuuint32_t box[3]     = {BW, BH, 32};
        cuuint32_t estr[3]    = {1, 1, 1};
        CUresult r = enc(&tmap, CU_TENSOR_MAP_DATA_TYPE_FLOAT32, 3, (void*)x,
                         dims, strides, box, estr,
                         CU_TENSOR_MAP_INTERLEAVE_NONE, CU_TENSOR_MAP_SWIZZLE_NONE,
                         CU_TENSOR_MAP_L2_PROMOTION_L2_128B,
                         CU_TENSOR_MAP_FLOAT_OOB_FILL_NONE);
        tma_ok = (r == CUDA_SUCCESS);
    }

    if (tma_ok) {
        static bool attr_set = false;
        if (!attr_set) {
            cudaFuncSetAttribute(gather_tma_kernel,
                                 cudaFuncAttributeMaxDynamicSharedMemorySize, SMEM_BYTES);
            attr_set = true;
        }
        gather_tma_kernel<<<M, 32, SMEM_BYTES>>>(tmap, idx, (float*)d_out);
    } else {
        gather_fallback_kernel<<<M * FB_SPLIT, FB_TPB>>>(x, idx, (float4*)d_out);
    }
}

// round 16
// speedup vs baseline: 1.1333x; 1.1333x over previous
#include <cuda_runtime.h>
#include <cstdint>

// GatherBlock: out[m, :, :, :] = x[b[m], :, yb[m]*16 : yb[m]*16+16, xb[m]*16 : xb[m]*16+16]
// x: (8, 64, 256, 256) fp32, indices: (1024, 3) int32, out: (1024, 64, 16, 16) fp32.
//
// R16 (final form): 4-way DRAM-row adjacency. All paths (LDG burst, double-
// buffer, persistent, TMA) hit the same ~4.6TB/s mixed-stream DRAM
// equilibrium with compulsory traffic, so the only residual lever is read
// row-buffer locality. The counting sort makes consecutive perm entries share
// (b,yb) (same 1KB DRAM rows, ascending xb). Each CTA processes a QUAD of
// consecutive sorted tiles; every thread issues the 4 tiles' loads for the
// same (c,row) back-to-back -> 4-deep same-row bursts at the controller.
// Proven burst structure: grid 4096, 128 thr, 8 front-batched LDG.128,
// __ldcg reads, __stcs streaming stores.

static constexpr int C = 64;
static constexpr int H = 256;
static constexpr int W = 256;
static constexpr int BH = 16;
static constexpr int BW = 16;
static constexpr int CHW = C * H * W;      // 4194304
static constexpr int HW = H * W;           // 65536
static constexpr int VEC_PER_M = C * BH * BW / 4;       // 4096 float4 per output block
static constexpr int SPLIT = 16;                        // chunks per quad
static constexpr int VEC_PER_CHUNK = VEC_PER_M / SPLIT; // 256 float4 per m per chunk
static constexpr int M_MAX = 1024;
static constexpr int BINS = 2048;                       // 8*16*16 tile ids
static constexpr int TPB = 128;                         // threads per gather CTA
static constexpr int LPM = VEC_PER_CHUNK / TPB;         // 2 float4 per thread per m

__device__ int g_perm[M_MAX];

__global__ __launch_bounds__(M_MAX, 1)
void sort_indices_kernel(const int* __restrict__ idx, int M)
{
    __shared__ unsigned hist[BINS];
    __shared__ unsigned warpsum[32];

    const int t = threadIdx.x;
    const int lane = t & 31;
    const int wid = t >> 5;

    hist[2 * t]     = 0;
    hist[2 * t + 1] = 0;
    __syncthreads();

    int key = 0;
    if (t < M) {
        const int b  = idx[3 * t + 0];
        const int yb = idx[3 * t + 1];
        const int xb = idx[3 * t + 2];
        key = (b << 8) | (yb << 4) | xb;   // (b,yb) groups contiguous, xb ascending
        atomicAdd(&hist[key], 1u);
    }
    __syncthreads();

    const unsigned a = hist[2 * t];
    const unsigned bcnt = hist[2 * t + 1];
    const unsigned s = a + bcnt;

    unsigned incl = s;
#pragma unroll
    for (int d = 1; d < 32; d <<= 1) {
        const unsigned n = __shfl_up_sync(0xFFFFFFFFu, incl, d);
        if (lane >= d) incl += n;
    }
    const unsigned thr_excl = incl - s;
    if (lane == 31) warpsum[wid] = incl;
    __syncthreads();

    if (wid == 0) {
        unsigned v = warpsum[lane];
        unsigned pv = v;
#pragma unroll
        for (int d = 1; d < 32; d <<= 1) {
            const unsigned n = __shfl_up_sync(0xFFFFFFFFu, pv, d);
            if (lane >= d) pv += n;
        }
        warpsum[lane] = pv - v;
    }
    __syncthreads();

    const unsigned base = warpsum[wid] + thr_excl;
    hist[2 * t]     = base;
    hist[2 * t + 1] = base + a;
    __syncthreads();

    if (t < M) {
        const unsigned pos = atomicAdd(&hist[key], 1u);
        g_perm[pos] = t;
    }
}

__global__ __launch_bounds__(TPB, 8)
void gather_block_kernel(const float* __restrict__ x,
                         const int* __restrict__ idx,
                         float4* __restrict__ out)
{
    const int p = blockIdx.x >> 4;          // quad index (0..255)
    const int q = blockIdx.x & 15;          // which sixteenth of each block

    const float* src[4];
    float4* dst[4];
#pragma unroll
    for (int u = 0; u < 4; u++) {
        const int m  = g_perm[4 * p + u];
        const int b  = idx[3 * m + 0];
        const int yb = idx[3 * m + 1];
        const int xb = idx[3 * m + 2];
        src[u] = x + (size_t)b * CHW + (size_t)(yb * BH) * W + (size_t)(xb * BW);
        dst[u] = out + (size_t)m * VEC_PER_M;
    }

    const int t = threadIdx.x;
    const int v0 = q * VEC_PER_CHUNK + t;   // first float4 index within each block

    // v in [0, 4096): c = v>>6, row i = (v>>2)&15, j-vector = v&3.
    // Tile-innermost load order: the 4 tiles' loads for the same (c,i) are
    // issued back-to-back, hitting the same 1KB DRAM row when the quad shares
    // (b,yb) (ascending xb within the row). All 8 loads front-batched.
    float4 r[4][LPM];
#pragma unroll
    for (int k = 0; k < LPM; k++) {
        const int v = v0 + k * TPB;
        const int c = v >> 6;
        const int i = (v >> 2) & 15;
        const int j = v & 3;
        const size_t off = (size_t)c * HW + (size_t)i * W;
#pragma unroll
        for (int u = 0; u < 4; u++) {
            r[u][k] = __ldcg(reinterpret_cast<const float4*>(src[u] + off) + j);
        }
    }
#pragma unroll
    for (int k = 0; k < LPM; k++) {
#pragma unroll
        for (int u = 0; u < 4; u++) {
            __stcs(dst[u] + v0 + k * TPB, r[u][k]);
        }
    }
}

extern "C" void kernel_launch(void* const* d_in, const int* in_sizes, int n_in,
                              void* d_out, int out_size)
{
    const float* x  = (const float*)d_in[0];
    const int* idx  = (const int*)d_in[1];
    float4* out     = (float4*)d_out;

    const int M = in_sizes[1] / 3;  // 1024
    sort_indices_kernel<<<1, M_MAX>>>(idx, M);
    gather_block_kernel<<<(M / 4) * SPLIT, TPB>>>(x, idx, out);
}

// round 17
// speedup vs baseline: 1.1346x; 1.0012x over previous
#include <cuda_runtime.h>
#include <cstdint>

// GatherBlock: out[m, :, :, :] = x[b[m], :, yb[m]*16 : yb[m]*16+16, xb[m]*16 : xb[m]*16+16]
// x: (8, 64, 256, 256) fp32, indices: (1024, 3) int32, out: (1024, 64, 16, 16) fp32.
//
// FINAL (R17): converged configuration. 16 rounds established that every
// execution path (LDG burst, double-buffered persistent, PDL, TMA, 1/2/4-tile
// row-adjacency) hits the same ~4.55TB/s mixed-stream DRAM equilibrium at
// compulsory traffic (~114MB). This is the empirically best-benched variant
// (R14 pair-adjacency, 27.104us) with stores grouped per destination (two
// dense 8KB write bursts per CTA instead of interleaved).
//   - counting-sort schedule: CTAs process tiles in (b,yb,xb) order (~free,
//     ~1us faster gather; same-(b,yb) pairs share 1KB DRAM rows)
//   - gather: grid 4096, 128 thr, 8 front-batched LDG.128 (__ldcg),
//     __stcs streaming stores.

static constexpr int C = 64;
static constexpr int H = 256;
static constexpr int W = 256;
static constexpr int BH = 16;
static constexpr int BW = 16;
static constexpr int CHW = C * H * W;      // 4194304
static constexpr int HW = H * W;           // 65536
static constexpr int VEC_PER_M = C * BH * BW / 4;       // 4096 float4 per output block
static constexpr int SPLIT = 8;                         // chunks per pair
static constexpr int VEC_PER_CHUNK = VEC_PER_M / SPLIT; // 512 float4 per m per chunk
static constexpr int M_MAX = 1024;
static constexpr int BINS = 2048;                       // 8*16*16 tile ids
static constexpr int TPB = 128;                         // threads per gather CTA
static constexpr int LPM = VEC_PER_CHUNK / TPB;         // 4 float4 per thread per m

__device__ int g_perm[M_MAX];

__global__ __launch_bounds__(M_MAX, 1)
void sort_indices_kernel(const int* __restrict__ idx, int M)
{
    __shared__ unsigned hist[BINS];
    __shared__ unsigned warpsum[32];

    const int t = threadIdx.x;
    const int lane = t & 31;
    const int wid = t >> 5;

    hist[2 * t]     = 0;
    hist[2 * t + 1] = 0;
    __syncthreads();

    int key = 0;
    if (t < M) {
        const int b  = idx[3 * t + 0];
        const int yb = idx[3 * t + 1];
        const int xb = idx[3 * t + 2];
        key = (b << 8) | (yb << 4) | xb;   // (b,yb) groups contiguous, xb ascending
        atomicAdd(&hist[key], 1u);
    }
    __syncthreads();

    const unsigned a = hist[2 * t];
    const unsigned bcnt = hist[2 * t + 1];
    const unsigned s = a + bcnt;

    unsigned incl = s;
#pragma unroll
    for (int d = 1; d < 32; d <<= 1) {
        const unsigned n = __shfl_up_sync(0xFFFFFFFFu, incl, d);
        if (lane >= d) incl += n;
    }
    const unsigned thr_excl = incl - s;
    if (lane == 31) warpsum[wid] = incl;
    __syncthreads();

    if (wid == 0) {
        unsigned v = warpsum[lane];
        unsigned pv = v;
#pragma unroll
        for (int d = 1; d < 32; d <<= 1) {
            const unsigned n = __shfl_up_sync(0xFFFFFFFFu, pv, d);
            if (lane >= d) pv += n;
        }
        warpsum[lane] = pv - v;
    }
    __syncthreads();

    const unsigned base = warpsum[wid] + thr_excl;
    hist[2 * t]     = base;
    hist[2 * t + 1] = base + a;
    __syncthreads();

    if (t < M) {
        const unsigned pos = atomicAdd(&hist[key], 1u);
        g_perm[pos] = t;
    }
}

__global__ __launch_bounds__(TPB, 8)
void gather_block_kernel(const float* __restrict__ x,
                         const int* __restrict__ idx,
                         float4* __restrict__ out)
{
    const int p = blockIdx.x >> 3;          // pair index (0..511)
    const int q = blockIdx.x & 7;           // which eighth of each block

    const int m0 = g_perm[2 * p];
    const int m1 = g_perm[2 * p + 1];

    const int b0  = idx[3 * m0 + 0];
    const int yb0 = idx[3 * m0 + 1];
    const int xb0 = idx[3 * m0 + 2];
    const int b1  = idx[3 * m1 + 0];
    const int yb1 = idx[3 * m1 + 1];
    const int xb1 = idx[3 * m1 + 2];

    const float* src0 = x + (size_t)b0 * CHW + (size_t)(yb0 * BH) * W + (size_t)(xb0 * BW);
    const float* src1 = x + (size_t)b1 * CHW + (size_t)(yb1 * BH) * W + (size_t)(xb1 * BW);
    float4* dst0 = out + (size_t)m0 * VEC_PER_M;
    float4* dst1 = out + (size_t)m1 * VEC_PER_M;

    const int t = threadIdx.x;
    const int v0 = q * VEC_PER_CHUNK + t;   // first float4 index within each block

    // v in [0, 4096): c = v>>6, row i = (v>>2)&15, j-vector = v&3.
    // Loads tile-innermost: m0/m1 accesses for the same (c,i) are adjacent,
    // hitting the same 1KB DRAM row when the pair shares (b,yb) (~7/8).
    float4 r0[LPM], r1[LPM];
#pragma unroll
    for (int k = 0; k < LPM; k++) {
        const int v = v0 + k * TPB;
        const int c = v >> 6;
        const int i = (v >> 2) & 15;
        const int j = v & 3;
        const size_t off = (size_t)c * HW + (size_t)i * W;
        r0[k] = __ldcg(reinterpret_cast<const float4*>(src0 + off) + j);
        r1[k] = __ldcg(reinterpret_cast<const float4*>(src1 + off) + j);
    }
    // Stores grouped per destination: two dense 8KB write bursts.
#pragma unroll
    for (int k = 0; k < LPM; k++) {
        __stcs(dst0 + v0 + k * TPB, r0[k]);
    }
#pragma unroll
    for (int k = 0; k < LPM; k++) {
        __stcs(dst1 + v0 + k * TPB, r1[k]);
    }
}

extern "C" void kernel_launch(void* const* d_in, const int* in_sizes, int n_in,
                              void* d_out, int out_size)
{
    const float* x  = (const float*)d_in[0];
    const int* idx  = (const int*)d_in[1];
    float4* out     = (float4*)d_out;

    const int M = in_sizes[1] / 3;  // 1024
    sort_indices_kernel<<<1, M_MAX>>>(idx, M);
    gather_block_kernel<<<(M / 2) * SPLIT, TPB>>>(x, idx, out);
}